// round 3
// baseline (speedup 1.0000x reference)
#include <cuda_runtime.h>
#include <cstdint>

// Problem constants (fixed shapes for this problem instance)
#define CC   128            // channels (K)
#define HH   96
#define WW   128
#define PP   (HH * WW)      // 12288 left pixels  (M)
#define HRR  96
#define WRR  128
#define QQ   (HRR * WRR)    // 12288 right pixels (N)

#define BM   128            // left-pixel tile per block
#define BN   64             // right-pixel tile per iteration
#define QS   12             // Q splits (grid.y)
#define QLEN (QQ / QS)      // 1024, divisible by BN
#define NTHREADS 256

#define SMEM_BYTES ((CC * BM + CC * BN) * 4)   // 64KB A + 32KB B = 98304

// Cross-block argmax combine scratch: packed (sortable_key << 32) | (~q_index).
// Larger packed value == larger corr value; on equal corr, smaller index wins
// (matches jnp.argmax first-index tie-break). 0 is below any real value's pack.
__device__ unsigned long long g_best[PP];

// ---------------- packed f32x2 helpers ----------------
__device__ __forceinline__ unsigned long long fma2(unsigned long long a,
                                                   unsigned long long b,
                                                   unsigned long long c) {
    unsigned long long d;
    asm("fma.rn.f32x2 %0, %1, %2, %3;" : "=l"(d) : "l"(a), "l"(b), "l"(c));
    return d;
}
__device__ __forceinline__ unsigned long long bcast2(float x) {
    unsigned long long d;
    asm("mov.b64 %0, {%1, %1};" : "=l"(d) : "f"(x));
    return d;
}
__device__ __forceinline__ float2 unpack2(unsigned long long v) {
    float2 r;
    asm("mov.b64 {%0, %1}, %2;" : "=f"(r.x), "=f"(r.y) : "l"(v));
    return r;
}
// Monotone float -> uint32 key (total order matching float order)
__device__ __forceinline__ unsigned int fkey(float f) {
    unsigned int b = __float_as_uint(f);
    return (b & 0x80000000u) ? ~b : (b | 0x80000000u);
}

// ---------------- kernels ----------------
__global__ void init_best_kernel() {
    int p = blockIdx.x * blockDim.x + threadIdx.x;
    if (p < PP) g_best[p] = 0ull;
}

__global__ void __launch_bounds__(NTHREADS, 2)
corr_argmax_kernel(const float* __restrict__ fl, const float* __restrict__ fr) {
    extern __shared__ float smem[];
    float* As = smem;            // [CC][BM]  (c-major rows of 128 left pixels)
    float* Bs = smem + CC * BM;  // [CC][BN]

    const int mt  = blockIdx.x;
    const int qsp = blockIdx.y;
    const int m0  = mt * BM;
    const int tid = threadIdx.x;
    const int tx  = tid & 15;    // 16 n-groups (tx*4 .. tx*4+3)
    const int ty  = tid >> 4;    // 16 m-groups (ty*8 .. ty*8+7)

    // Load A tile once: CC*BM floats = 4096 float4, 16 per thread. Coalesced.
    #pragma unroll
    for (int i = 0; i < (CC * BM / 4) / NTHREADS; ++i) {
        int idx = i * NTHREADS + tid;
        int c = idx >> 5;          // 32 float4 per channel row
        int x = idx & 31;
        reinterpret_cast<float4*>(As)[idx] =
            *reinterpret_cast<const float4*>(fl + (size_t)c * PP + m0 + x * 4);
    }

    unsigned long long best[8];
    #pragma unroll
    for (int i = 0; i < 8; ++i) best[i] = 0ull;

    const int qbeg = qsp * QLEN;
    for (int qb = qbeg; qb < qbeg + QLEN; qb += BN) {
        __syncthreads();
        // Load B tile: CC*BN floats = 2048 float4, 8 per thread. Coalesced; L2-resident.
        #pragma unroll
        for (int i = 0; i < (CC * BN / 4) / NTHREADS; ++i) {
            int idx = i * NTHREADS + tid;
            int c = idx >> 4;       // 16 float4 per channel row
            int x = idx & 15;
            reinterpret_cast<float4*>(Bs)[idx] =
                *reinterpret_cast<const float4*>(fr + (size_t)c * QQ + qb + x * 4);
        }
        __syncthreads();

        // acc[n][mp] = packed pair (m = ty*8 + 2*mp, ty*8 + 2*mp+1) x (q = qb + tx*4 + n)
        unsigned long long acc[4][4];
        #pragma unroll
        for (int n = 0; n < 4; ++n)
            #pragma unroll
            for (int m = 0; m < 4; ++m) acc[n][m] = 0ull;  // == (0.0f, 0.0f)

        #pragma unroll 8
        for (int k = 0; k < CC; ++k) {
            // 8 A values for this thread's m rows, read directly as 4 packed pairs
            const ulonglong2* arow =
                reinterpret_cast<const ulonglong2*>(As + k * BM + ty * 8);
            ulonglong2 A01 = arow[0];
            ulonglong2 A23 = arow[1];
            unsigned long long a0 = A01.x, a1 = A01.y, a2 = A23.x, a3 = A23.y;
            float4 bv = *reinterpret_cast<const float4*>(Bs + k * BN + tx * 4);

            unsigned long long b;
            b = bcast2(bv.x);
            acc[0][0] = fma2(a0, b, acc[0][0]); acc[0][1] = fma2(a1, b, acc[0][1]);
            acc[0][2] = fma2(a2, b, acc[0][2]); acc[0][3] = fma2(a3, b, acc[0][3]);
            b = bcast2(bv.y);
            acc[1][0] = fma2(a0, b, acc[1][0]); acc[1][1] = fma2(a1, b, acc[1][1]);
            acc[1][2] = fma2(a2, b, acc[1][2]); acc[1][3] = fma2(a3, b, acc[1][3]);
            b = bcast2(bv.z);
            acc[2][0] = fma2(a0, b, acc[2][0]); acc[2][1] = fma2(a1, b, acc[2][1]);
            acc[2][2] = fma2(a2, b, acc[2][2]); acc[2][3] = fma2(a3, b, acc[2][3]);
            b = bcast2(bv.w);
            acc[3][0] = fma2(a0, b, acc[3][0]); acc[3][1] = fma2(a1, b, acc[3][1]);
            acc[3][2] = fma2(a2, b, acc[3][2]); acc[3][3] = fma2(a3, b, acc[3][3]);
        }

        // Fold this q-tile into running per-row best
        #pragma unroll
        for (int n = 0; n < 4; ++n) {
            unsigned int q   = (unsigned int)(qb + tx * 4 + n);
            unsigned int inv = 0xFFFFFFFFu - q;
            #pragma unroll
            for (int mp = 0; mp < 4; ++mp) {
                float2 v = unpack2(acc[n][mp]);
                unsigned long long p0 = ((unsigned long long)fkey(v.x) << 32) | inv;
                unsigned long long p1 = ((unsigned long long)fkey(v.y) << 32) | inv;
                if (p0 > best[2 * mp])     best[2 * mp]     = p0;
                if (p1 > best[2 * mp + 1]) best[2 * mp + 1] = p1;
            }
        }
    }

    // Reduce over the 16 tx lanes (lane = (ty&1)*16 + tx, xor 1..8 stays in-group)
    #pragma unroll
    for (int off = 1; off < 16; off <<= 1) {
        #pragma unroll
        for (int i = 0; i < 8; ++i) {
            unsigned long long o = __shfl_xor_sync(0xFFFFFFFFu, best[i], off);
            if (o > best[i]) best[i] = o;
        }
    }
    if (tx == 0) {
        #pragma unroll
        for (int i = 0; i < 8; ++i)
            atomicMax(&g_best[m0 + ty * 8 + i], best[i]);
    }
}

__global__ void decode_kernel(float* __restrict__ out,
                              const int* __restrict__ sxp,
                              const int* __restrict__ syp) {
    int p = blockIdx.x * blockDim.x + threadIdx.x;
    if (p >= PP) return;
    int sx = sxp ? *sxp : 4;
    int sy = syp ? *syp : 4;

    unsigned long long pk = g_best[p];
    unsigned int key = (unsigned int)(pk >> 32);
    unsigned int idx = 0xFFFFFFFFu - (unsigned int)(pk & 0xFFFFFFFFu);
    float val = (key & 0x80000000u) ? __uint_as_float(key ^ 0x80000000u)
                                    : __uint_as_float(~key);
    int h = p / WW, w = p % WW;
    int i = (int)(idx / WRR), j = (int)(idx % WRR);

    // u = -((idx % W_R)*scale_x - x), v = -((idx // W_R)*scale_y - y)
    out[2 * p + 0]   = (float)(w - j * sx);
    out[2 * p + 1]   = (float)(h - i * sy);
    out[2 * PP + p]  = val;   // flow_cost after flow in tuple order
}

// ---------------- launch ----------------
extern "C" void kernel_launch(void* const* d_in, const int* in_sizes, int n_in,
                              void* d_out, int out_size) {
    const float* fl = (const float*)d_in[0];
    const float* fr = (const float*)d_in[1];
    const int* sxp = (n_in > 2) ? (const int*)d_in[2] : nullptr;
    const int* syp = (n_in > 3) ? (const int*)d_in[3] : nullptr;
    float* out = (float*)d_out;
    (void)in_sizes; (void)out_size;

    // Opt-in to >48KB dynamic shared memory (idempotent, not a stream op).
    cudaFuncSetAttribute(corr_argmax_kernel,
                         cudaFuncAttributeMaxDynamicSharedMemorySize, SMEM_BYTES);

    init_best_kernel<<<(PP + 255) / 256, 256>>>();
    corr_argmax_kernel<<<dim3(PP / BM, QS), NTHREADS, SMEM_BYTES>>>(fl, fr);
    decode_kernel<<<(PP + 255) / 256, 256>>>(out, sxp, syp);
}